// round 1
// baseline (speedup 1.0000x reference)
#include <cuda_runtime.h>
#include <cuda_bf16.h>

// ---------------------------------------------------------------------------
// Model constants
// ---------------------------------------------------------------------------
#define BATCH     8
#define SEQ       512
#define INPUT_DIM 32
#define DMODEL    256
#define NLAYERS   4
#define DSTATE    16
#define DCONV     4
#define DINNER    512            // 2 * DMODEL
#define DTRANK    16
#define MROWS     (BATCH*SEQ)    // 4096
#define LN_EPS    1e-5f

// ---------------------------------------------------------------------------
// Device scratch (allocation-free rule: use __device__ globals)
// ---------------------------------------------------------------------------
__device__ float g_h  [MROWS * DMODEL];        // residual stream
__device__ float g_xn [MROWS * DMODEL];        // layernorm output
__device__ float g_xz [MROWS * 2 * DINNER];    // in_proj output (u | z)
__device__ float g_u  [MROWS * DINNER];        // conv+silu output
__device__ float g_dbl[MROWS * 48];            // x_proj output (dt_r | B | C)
__device__ float g_dt [MROWS * DINNER];        // softplus(dt)
__device__ float g_y  [MROWS * DINNER];        // scan output (gated)
__device__ float g_t1 [BATCH * DMODEL];        // head hidden

// ---------------------------------------------------------------------------
// Generic NT SGEMM:  C[m,n] = sum_k A[m,k] * W[n,k]  (+bias, +residual, act)
// A: M x K (lda), W: N x K (ldw), C: M x N (ldc). K % 16 == 0, M % 64 == 0.
// act: 0 = none, 1 = softplus
// ---------------------------------------------------------------------------
#define BM 64
#define BN 64
#define BKQ 16
#define TM 4
#define TN 4

__global__ __launch_bounds__(256)
void sgemm_nt_kernel(const float* __restrict__ A, int lda,
                     const float* __restrict__ W, int ldw,
                     const float* __restrict__ bias,
                     const float* __restrict__ residual,
                     float* __restrict__ C, int ldc,
                     int M, int N, int K, int act)
{
    __shared__ float As[BKQ][BM + 4];
    __shared__ float Ws[BKQ][BN + 4];

    const int tid  = threadIdx.x;
    const int tx   = tid & 15;          // 0..15 (N dir)
    const int ty   = tid >> 4;          // 0..15 (M dir)
    const int row0 = blockIdx.y * BM;
    const int col0 = blockIdx.x * BN;

    const int lr = tid >> 2;            // 0..63  (tile row for loads)
    const int lk = (tid & 3) * 4;       // 0,4,8,12

    float acc[TM][TN];
#pragma unroll
    for (int i = 0; i < TM; i++)
#pragma unroll
        for (int j = 0; j < TN; j++) acc[i][j] = 0.f;

    for (int k0 = 0; k0 < K; k0 += BKQ) {
        // load A tile (rows always valid: M % 64 == 0)
        float4 av = *(const float4*)(A + (size_t)(row0 + lr) * lda + k0 + lk);
        As[lk + 0][lr] = av.x; As[lk + 1][lr] = av.y;
        As[lk + 2][lr] = av.z; As[lk + 3][lr] = av.w;

        // load W tile with N guard
        float4 wv = make_float4(0.f, 0.f, 0.f, 0.f);
        if (col0 + lr < N)
            wv = *(const float4*)(W + (size_t)(col0 + lr) * ldw + k0 + lk);
        Ws[lk + 0][lr] = wv.x; Ws[lk + 1][lr] = wv.y;
        Ws[lk + 2][lr] = wv.z; Ws[lk + 3][lr] = wv.w;

        __syncthreads();

#pragma unroll
        for (int kk = 0; kk < BKQ; kk++) {
            float a[TM], w[TN];
#pragma unroll
            for (int i = 0; i < TM; i++) a[i] = As[kk][ty * TM + i];
#pragma unroll
            for (int j = 0; j < TN; j++) w[j] = Ws[kk][tx * TN + j];
#pragma unroll
            for (int i = 0; i < TM; i++)
#pragma unroll
                for (int j = 0; j < TN; j++) acc[i][j] += a[i] * w[j];
        }
        __syncthreads();
    }

#pragma unroll
    for (int i = 0; i < TM; i++) {
        int r = row0 + ty * TM + i;
#pragma unroll
        for (int j = 0; j < TN; j++) {
            int c = col0 + tx * TN + j;
            if (c < N) {
                float v = acc[i][j];
                if (bias)     v += bias[c];
                if (residual) v += residual[(size_t)r * ldc + c];
                if (act == 1) {  // softplus
                    v = (v > 20.f) ? v : log1pf(__expf(v));
                }
                C[(size_t)r * ldc + c] = v;
            }
        }
    }
}

// ---------------------------------------------------------------------------
// LayerNorm: one warp per row of 256
// ---------------------------------------------------------------------------
__global__ __launch_bounds__(256)
void ln_kernel(const float* __restrict__ h,
               const float* __restrict__ w, const float* __restrict__ b,
               float* __restrict__ out)
{
    int row  = blockIdx.x * 8 + (threadIdx.x >> 5);
    int lane = threadIdx.x & 31;
    const float* x = h + (size_t)row * DMODEL;

    float v[8];
    float s = 0.f, ss = 0.f;
#pragma unroll
    for (int i = 0; i < 8; i++) {
        v[i] = x[lane + i * 32];
        s  += v[i];
        ss += v[i] * v[i];
    }
#pragma unroll
    for (int off = 16; off > 0; off >>= 1) {
        s  += __shfl_xor_sync(0xffffffffu, s,  off);
        ss += __shfl_xor_sync(0xffffffffu, ss, off);
    }
    float mean = s * (1.f / DMODEL);
    float var  = ss * (1.f / DMODEL) - mean * mean;
    float rstd = rsqrtf(var + LN_EPS);

    float* o = out + (size_t)row * DMODEL;
#pragma unroll
    for (int i = 0; i < 8; i++) {
        int c = lane + i * 32;
        o[c] = (v[i] - mean) * rstd * w[c] + b[c];
    }
}

// ---------------------------------------------------------------------------
// Causal depthwise conv (width 4) + SiLU, reading u-half of xz
// ---------------------------------------------------------------------------
__global__ __launch_bounds__(256)
void conv_silu_kernel(const float* __restrict__ xz,
                      const float* __restrict__ cw, const float* __restrict__ cb,
                      float* __restrict__ u)
{
    int idx = blockIdx.x * blockDim.x + threadIdx.x;   // over 8*512*512
    if (idx >= MROWS * DINNER) return;
    int d = idx & (DINNER - 1);
    int t = (idx >> 9) & (SEQ - 1);
    int b = idx >> 18;

    const float* base = xz + (size_t)(b * SEQ) * (2 * DINNER) + d;
    float acc = cb[d];
#pragma unroll
    for (int k = 0; k < DCONV; k++) {
        int tt = t - (DCONV - 1) + k;
        if (tt >= 0) acc += base[(size_t)tt * (2 * DINNER)] * cw[d * DCONV + k];
    }
    // silu
    u[idx] = acc / (1.f + __expf(-acc));
}

// ---------------------------------------------------------------------------
// Selective scan: thread = (b, d, s). 16-lane shfl reduce over states.
// Fuses +u*D and *silu(z) gate.
// ---------------------------------------------------------------------------
__global__ __launch_bounds__(256)
void scan_kernel(const float* __restrict__ dt, const float* __restrict__ u,
                 const float* __restrict__ dbl, const float* __restrict__ xz,
                 const float* __restrict__ A_log, const float* __restrict__ Dvec,
                 float* __restrict__ y)
{
    int tid  = blockIdx.x * blockDim.x + threadIdx.x;
    int s    = tid & (DSTATE - 1);
    int pair = tid >> 4;              // (b,d)
    int d    = pair & (DINNER - 1);
    int b    = pair >> 9;

    float A  = -__expf(A_log[d * DSTATE + s]);
    float Dp = Dvec[d];
    float h  = 0.f;

    const float* dt_p = dt  + (size_t)b * SEQ * DINNER + d;
    const float* u_p  = u   + (size_t)b * SEQ * DINNER + d;
    const float* bc_p = dbl + (size_t)b * SEQ * 48;
    const float* z_p  = xz  + (size_t)b * SEQ * (2 * DINNER) + DINNER + d;
    float*       y_p  = y   + (size_t)b * SEQ * DINNER + d;

    for (int t = 0; t < SEQ; t++) {
        float dtv = dt_p[(size_t)t * DINNER];
        float uv  = u_p [(size_t)t * DINNER];
        float Bv  = bc_p[t * 48 + DTRANK + s];
        float Cv  = bc_p[t * 48 + DTRANK + DSTATE + s];

        h = __expf(dtv * A) * h + dtv * uv * Bv;
        float yv = h * Cv;
        yv += __shfl_xor_sync(0xffffffffu, yv, 8);
        yv += __shfl_xor_sync(0xffffffffu, yv, 4);
        yv += __shfl_xor_sync(0xffffffffu, yv, 2);
        yv += __shfl_xor_sync(0xffffffffu, yv, 1);

        if (s == 0) {
            float z   = z_p[(size_t)t * (2 * DINNER)];
            float out = (yv + uv * Dp) * (z / (1.f + __expf(-z)));
            y_p[(size_t)t * DINNER] = out;
        }
    }
}

// ---------------------------------------------------------------------------
// Head: t1 = relu(h_last @ w1^T + b1); out = t1 @ w2^T + b2
// ---------------------------------------------------------------------------
__global__ __launch_bounds__(256)
void head1_kernel(const float* __restrict__ h,
                  const float* __restrict__ w1, const float* __restrict__ b1,
                  float* __restrict__ t1)
{
    __shared__ float hs[DMODEL];
    int b = blockIdx.x;
    int n = threadIdx.x;
    hs[n] = h[((size_t)b * SEQ + (SEQ - 1)) * DMODEL + n];
    __syncthreads();

    const float4* wp = (const float4*)(w1 + (size_t)n * DMODEL);
    float acc = b1[n];
#pragma unroll 8
    for (int k = 0; k < DMODEL / 4; k++) {
        float4 w4 = wp[k];
        acc += hs[4*k+0]*w4.x + hs[4*k+1]*w4.y + hs[4*k+2]*w4.z + hs[4*k+3]*w4.w;
    }
    t1[b * DMODEL + n] = fmaxf(acc, 0.f);
}

__global__ __launch_bounds__(32)
void head2_kernel(const float* __restrict__ t1,
                  const float* __restrict__ w2, const float* __restrict__ b2,
                  float* __restrict__ out)
{
    int b = blockIdx.x;
    int lane = threadIdx.x;
    float acc = 0.f;
#pragma unroll
    for (int k = lane; k < DMODEL; k += 32)
        acc += t1[b * DMODEL + k] * w2[k];
#pragma unroll
    for (int off = 16; off > 0; off >>= 1)
        acc += __shfl_xor_sync(0xffffffffu, acc, off);
    if (lane == 0) out[b] = acc + b2[0];
}

// ---------------------------------------------------------------------------
// Host launcher
// ---------------------------------------------------------------------------
extern "C" void kernel_launch(void* const* d_in, const int* in_sizes, int n_in,
                              void* d_out, int out_size)
{
    const float* x            = (const float*)d_in[0];   // (8,512,32)
    const float* input_proj_w = (const float*)d_in[1];   // (256,32)
    const float* input_proj_b = (const float*)d_in[2];   // (256)
    const float* ln_w         = (const float*)d_in[3];   // (4,256)
    const float* ln_b         = (const float*)d_in[4];   // (4,256)
    const float* in_proj_w    = (const float*)d_in[5];   // (4,1024,256)
    const float* conv_w       = (const float*)d_in[6];   // (4,512,4)
    const float* conv_b       = (const float*)d_in[7];   // (4,512)
    const float* x_proj_w     = (const float*)d_in[8];   // (4,48,512)
    const float* dt_proj_w    = (const float*)d_in[9];   // (4,512,16)
    const float* dt_proj_b    = (const float*)d_in[10];  // (4,512)
    const float* A_log        = (const float*)d_in[11];  // (4,512,16)
    const float* Dvec         = (const float*)d_in[12];  // (4,512)
    const float* out_proj_w   = (const float*)d_in[13];  // (4,256,512)
    const float* head_w1      = (const float*)d_in[14];  // (256,256)
    const float* head_b1      = (const float*)d_in[15];  // (256)
    const float* head_w2      = (const float*)d_in[16];  // (1,256)
    const float* head_b2      = (const float*)d_in[17];  // (1)
    float* out = (float*)d_out;

    float *p_h, *p_xn, *p_xz, *p_u, *p_dbl, *p_dt, *p_y, *p_t1;
    cudaGetSymbolAddress((void**)&p_h,   g_h);
    cudaGetSymbolAddress((void**)&p_xn,  g_xn);
    cudaGetSymbolAddress((void**)&p_xz,  g_xz);
    cudaGetSymbolAddress((void**)&p_u,   g_u);
    cudaGetSymbolAddress((void**)&p_dbl, g_dbl);
    cudaGetSymbolAddress((void**)&p_dt,  g_dt);
    cudaGetSymbolAddress((void**)&p_y,   g_y);
    cudaGetSymbolAddress((void**)&p_t1,  g_t1);

    // input projection: h = x @ input_proj_w^T + b   (M=4096, N=256, K=32)
    {
        dim3 grid((DMODEL + BN - 1) / BN, MROWS / BM);
        sgemm_nt_kernel<<<grid, 256>>>(x, INPUT_DIM, input_proj_w, INPUT_DIM,
                                       input_proj_b, nullptr,
                                       p_h, DMODEL, MROWS, DMODEL, INPUT_DIM, 0);
    }

    for (int l = 0; l < NLAYERS; l++) {
        // 1. layernorm
        ln_kernel<<<MROWS / 8, 256>>>(p_h, ln_w + l * DMODEL, ln_b + l * DMODEL, p_xn);

        // 2. in_proj: xz = xn @ W^T  (N=1024, K=256)
        {
            dim3 grid((2 * DINNER) / BN, MROWS / BM);
            sgemm_nt_kernel<<<grid, 256>>>(p_xn, DMODEL,
                                           in_proj_w + (size_t)l * 2 * DINNER * DMODEL, DMODEL,
                                           nullptr, nullptr,
                                           p_xz, 2 * DINNER, MROWS, 2 * DINNER, DMODEL, 0);
        }

        // 3. conv + silu -> u
        conv_silu_kernel<<<(MROWS * DINNER) / 256, 256>>>(
            p_xz, conv_w + l * DINNER * DCONV, conv_b + l * DINNER, p_u);

        // 4. x_proj: dbl = u @ W^T  (N=48, K=512)
        {
            dim3 grid(1, MROWS / BM);
            sgemm_nt_kernel<<<grid, 256>>>(p_u, DINNER,
                                           x_proj_w + (size_t)l * 48 * DINNER, DINNER,
                                           nullptr, nullptr,
                                           p_dbl, 48, MROWS, 48, DINNER, 0);
        }

        // 5. dt = softplus(dbl[:, :16] @ dt_proj_w^T + dt_proj_b)  (N=512, K=16)
        {
            dim3 grid(DINNER / BN, MROWS / BM);
            sgemm_nt_kernel<<<grid, 256>>>(p_dbl, 48,
                                           dt_proj_w + (size_t)l * DINNER * DTRANK, DTRANK,
                                           dt_proj_b + l * DINNER, nullptr,
                                           p_dt, DINNER, MROWS, DINNER, DTRANK, 1);
        }

        // 6. selective scan (+u*D, *silu(z))
        scan_kernel<<<(MROWS * DSTATE) / 256, 256>>>(
            p_dt, p_u, p_dbl, p_xz,
            A_log + (size_t)l * DINNER * DSTATE, Dvec + l * DINNER, p_y);

        // 7. out_proj with residual: h = h + y @ W^T  (N=256, K=512)
        {
            dim3 grid(DMODEL / BN, MROWS / BM);
            sgemm_nt_kernel<<<grid, 256>>>(p_y, DINNER,
                                           out_proj_w + (size_t)l * DMODEL * DINNER, DINNER,
                                           nullptr, p_h,
                                           p_h, DMODEL, MROWS, DMODEL, DINNER, 0);
        }
    }

    // head
    head1_kernel<<<BATCH, DMODEL>>>(p_h, head_w1, head_b1, p_t1);
    head2_kernel<<<BATCH, 32>>>(p_t1, head_w2, head_b2, out);
}

// round 2
// speedup vs baseline: 1.0839x; 1.0839x over previous
#include <cuda_runtime.h>
#include <cuda_bf16.h>

// ---------------------------------------------------------------------------
// Model constants
// ---------------------------------------------------------------------------
#define BATCH     8
#define SEQ       512
#define INPUT_DIM 32
#define DMODEL    256
#define NLAYERS   4
#define DSTATE    16
#define DCONV     4
#define DINNER    512            // 2 * DMODEL
#define DTRANK    16
#define MROWS     (BATCH*SEQ)    // 4096
#define LN_EPS    1e-5f

// ---------------------------------------------------------------------------
// Device scratch (allocation-free rule: use __device__ globals)
// ---------------------------------------------------------------------------
__device__ float g_h   [MROWS * DMODEL];        // residual stream
__device__ float g_xn  [MROWS * DMODEL];        // layernorm output
__device__ float g_xz  [MROWS * 2 * DINNER];    // in_proj output (u | z)
__device__ float g_u   [MROWS * DINNER];        // conv+silu output
__device__ float g_dbl [MROWS * 48];            // x_proj output (dt_r | B | C)
__device__ float g_dt  [MROWS * DINNER];        // softplus(dt)
__device__ float g_y   [MROWS * DINNER];        // scan output (gated)
__device__ float g_t1  [BATCH * DMODEL];        // head hidden
__device__ float g_part[2 * MROWS * DMODEL];    // split-K partials (2.1M floats)

// ---------------------------------------------------------------------------
// NT SGEMM, 128x64 CTA tile, BK=16, double-buffered SMEM, reg prefetch.
//   C[z][m,n] = sum_{k in z-th slice} A[m, z*Klen + k] * W[n, k_local...]
// Grid: (ceil(N/64), M/128, nsplit). Each z handles Klen columns of A starting
// at z*Klen, and writes to C + z*zstride (zstride=0 when nsplit==1).
// W is indexed from its own k=0 for z=0 only when nsplit==1; for split-K the
// W slice offset must match A's: we pass W already offset per... NO — W offset
// is handled inside via z*Klen as well (same k-slice of W).
// act: 0 none, 1 softplus. bias may be null.
// Requirements: M % 128 == 0, Klen % 16 == 0, f4 alignment of rows.
// ---------------------------------------------------------------------------
#define BM 128
#define BN 64
#define BK 16

__global__ __launch_bounds__(256)
void gemm_nt(const float* __restrict__ A, int lda,
             const float* __restrict__ W, int ldw,
             const float* __restrict__ bias,
             float* __restrict__ C, int ldc, size_t zstride,
             int N, int Klen, int act)
{
    __shared__ float As[2][BK][BM + 8];
    __shared__ float Ws[2][BK][BN + 8];

    const int tid  = threadIdx.x;
    const int tx   = tid & 15;           // n dir, 16
    const int ty   = tid >> 4;           // m dir, 16
    const int m0   = ty * 8;
    const int n0   = tx * 4;
    const int row0 = blockIdx.y * BM;
    const int col0 = blockIdx.x * BN;
    const int z    = blockIdx.z;

    const int kofs = z * Klen;           // k slice start (both A and W)
    C += (size_t)z * zstride;

    const int arow = tid >> 2;           // 0..63
    const int akq  = (tid & 3) * 4;      // 0,4,8,12

    const bool wvalid = (col0 + arow) < N;

    float4 a0v, a1v, wv;
    const int ntiles = Klen / BK;

    // ---- prologue: load tile 0 ----
    {
        const float* Ap = A + kofs + akq;
        a0v = *(const float4*)(Ap + (size_t)(row0 + arow)      * lda);
        a1v = *(const float4*)(Ap + (size_t)(row0 + arow + 64) * lda);
        wv  = wvalid ? *(const float4*)(W + (size_t)(col0 + arow) * ldw + kofs + akq)
                     : make_float4(0.f, 0.f, 0.f, 0.f);
    }
#pragma unroll
    for (int c = 0; c < 4; c++) {
        As[0][akq + c][arow]      = (&a0v.x)[c];
        As[0][akq + c][arow + 64] = (&a1v.x)[c];
        Ws[0][akq + c][arow]      = (&wv.x)[c];
    }
    __syncthreads();

    float acc[8][4];
#pragma unroll
    for (int i = 0; i < 8; i++)
#pragma unroll
        for (int j = 0; j < 4; j++) acc[i][j] = 0.f;

    for (int t = 0; t < ntiles; t++) {
        const int cur = t & 1;

        // prefetch next tile into registers
        if (t + 1 < ntiles) {
            const float* Ap = A + kofs + (t + 1) * BK + akq;
            a0v = *(const float4*)(Ap + (size_t)(row0 + arow)      * lda);
            a1v = *(const float4*)(Ap + (size_t)(row0 + arow + 64) * lda);
            wv  = wvalid ? *(const float4*)(W + (size_t)(col0 + arow) * ldw
                                            + kofs + (t + 1) * BK + akq)
                         : make_float4(0.f, 0.f, 0.f, 0.f);
        }

        // compute current tile
#pragma unroll
        for (int kk = 0; kk < BK; kk++) {
            float4 a01 = *(const float4*)&As[cur][kk][m0];
            float4 a23 = *(const float4*)&As[cur][kk][m0 + 4];
            float4 w4  = *(const float4*)&Ws[cur][kk][n0];
            float a[8] = {a01.x, a01.y, a01.z, a01.w, a23.x, a23.y, a23.z, a23.w};
            float w[4] = {w4.x, w4.y, w4.z, w4.w};
#pragma unroll
            for (int i = 0; i < 8; i++)
#pragma unroll
                for (int j = 0; j < 4; j++)
                    acc[i][j] = fmaf(a[i], w[j], acc[i][j]);
        }

        // store next tile to the other buffer (safe: last read of it was
        // compute(t-1), already fenced by the sync at end of iter t-1)
        if (t + 1 < ntiles) {
            const int nxt = cur ^ 1;
#pragma unroll
            for (int c = 0; c < 4; c++) {
                As[nxt][akq + c][arow]      = (&a0v.x)[c];
                As[nxt][akq + c][arow + 64] = (&a1v.x)[c];
                Ws[nxt][akq + c][arow]      = (&wv.x)[c];
            }
            __syncthreads();
        }
    }

    // ---- epilogue ----
#pragma unroll
    for (int i = 0; i < 8; i++) {
        const int r = row0 + m0 + i;
        float* Crow = C + (size_t)r * ldc;
#pragma unroll
        for (int j = 0; j < 4; j++) {
            const int c = col0 + n0 + j;
            if (c < N) {
                float v = acc[i][j];
                if (bias) v += bias[c];
                if (act == 1) v = (v > 20.f) ? v : log1pf(__expf(v));
                Crow[c] = v;
            }
        }
    }
}

// ---------------------------------------------------------------------------
// Split-K reduce: out[i] = (resid?resid[i]:0) + sum_z part[z*zstride + i]
// n must be a multiple of 4*blockDim*gridDim stride handling; we launch exact.
// ---------------------------------------------------------------------------
__global__ __launch_bounds__(256)
void reduce_kernel(const float* __restrict__ part, size_t zstride, int nz,
                   const float* __restrict__ resid,
                   float* __restrict__ out, int n)
{
    int i = (blockIdx.x * blockDim.x + threadIdx.x) * 4;
    if (i >= n) return;
    float4 s = resid ? *(const float4*)(resid + i) : make_float4(0.f,0.f,0.f,0.f);
    for (int zi = 0; zi < nz; zi++) {
        float4 p = *(const float4*)(part + (size_t)zi * zstride + i);
        s.x += p.x; s.y += p.y; s.z += p.z; s.w += p.w;
    }
    *(float4*)(out + i) = s;
}

// ---------------------------------------------------------------------------
// LayerNorm: one warp per row of 256
// ---------------------------------------------------------------------------
__global__ __launch_bounds__(256)
void ln_kernel(const float* __restrict__ h,
               const float* __restrict__ w, const float* __restrict__ b,
               float* __restrict__ out)
{
    int row  = blockIdx.x * 8 + (threadIdx.x >> 5);
    int lane = threadIdx.x & 31;
    const float* x = h + (size_t)row * DMODEL;

    float v[8];
    float s = 0.f, ss = 0.f;
#pragma unroll
    for (int i = 0; i < 8; i++) {
        v[i] = x[lane + i * 32];
        s  += v[i];
        ss += v[i] * v[i];
    }
#pragma unroll
    for (int off = 16; off > 0; off >>= 1) {
        s  += __shfl_xor_sync(0xffffffffu, s,  off);
        ss += __shfl_xor_sync(0xffffffffu, ss, off);
    }
    float mean = s * (1.f / DMODEL);
    float var  = ss * (1.f / DMODEL) - mean * mean;
    float rstd = rsqrtf(var + LN_EPS);

    float* o = out + (size_t)row * DMODEL;
#pragma unroll
    for (int i = 0; i < 8; i++) {
        int c = lane + i * 32;
        o[c] = (v[i] - mean) * rstd * w[c] + b[c];
    }
}

// ---------------------------------------------------------------------------
// Causal depthwise conv (width 4) + SiLU, reading u-half of xz
// ---------------------------------------------------------------------------
__global__ __launch_bounds__(256)
void conv_silu_kernel(const float* __restrict__ xz,
                      const float* __restrict__ cw, const float* __restrict__ cb,
                      float* __restrict__ u)
{
    int idx = blockIdx.x * blockDim.x + threadIdx.x;   // over 8*512*512
    if (idx >= MROWS * DINNER) return;
    int d = idx & (DINNER - 1);
    int t = (idx >> 9) & (SEQ - 1);
    int b = idx >> 18;

    const float* base = xz + (size_t)(b * SEQ) * (2 * DINNER) + d;
    float acc = cb[d];
#pragma unroll
    for (int k = 0; k < DCONV; k++) {
        int tt = t - (DCONV - 1) + k;
        if (tt >= 0) acc += base[(size_t)tt * (2 * DINNER)] * cw[d * DCONV + k];
    }
    u[idx] = acc / (1.f + __expf(-acc));
}

// ---------------------------------------------------------------------------
// Selective scan: thread = (b, d, s). 16-lane shfl reduce over states.
// Fuses +u*D and *silu(z) gate.
// ---------------------------------------------------------------------------
__global__ __launch_bounds__(256)
void scan_kernel(const float* __restrict__ dt, const float* __restrict__ u,
                 const float* __restrict__ dbl, const float* __restrict__ xz,
                 const float* __restrict__ A_log, const float* __restrict__ Dvec,
                 float* __restrict__ y)
{
    int tid  = blockIdx.x * blockDim.x + threadIdx.x;
    int s    = tid & (DSTATE - 1);
    int pair = tid >> 4;              // (b,d)
    int d    = pair & (DINNER - 1);
    int b    = pair >> 9;

    float A  = -__expf(A_log[d * DSTATE + s]);
    float Dp = Dvec[d];
    float h  = 0.f;

    const float* dt_p = dt  + (size_t)b * SEQ * DINNER + d;
    const float* u_p  = u   + (size_t)b * SEQ * DINNER + d;
    const float* bc_p = dbl + (size_t)b * SEQ * 48;
    const float* z_p  = xz  + (size_t)b * SEQ * (2 * DINNER) + DINNER + d;
    float*       y_p  = y   + (size_t)b * SEQ * DINNER + d;

    for (int t = 0; t < SEQ; t++) {
        float dtv = dt_p[(size_t)t * DINNER];
        float uv  = u_p [(size_t)t * DINNER];
        float Bv  = bc_p[t * 48 + DTRANK + s];
        float Cv  = bc_p[t * 48 + DTRANK + DSTATE + s];

        h = __expf(dtv * A) * h + dtv * uv * Bv;
        float yv = h * Cv;
        yv += __shfl_xor_sync(0xffffffffu, yv, 8);
        yv += __shfl_xor_sync(0xffffffffu, yv, 4);
        yv += __shfl_xor_sync(0xffffffffu, yv, 2);
        yv += __shfl_xor_sync(0xffffffffu, yv, 1);

        if (s == 0) {
            float zv  = z_p[(size_t)t * (2 * DINNER)];
            float out = (yv + uv * Dp) * (zv / (1.f + __expf(-zv)));
            y_p[(size_t)t * DINNER] = out;
        }
    }
}

// ---------------------------------------------------------------------------
// Head: t1 = relu(h_last @ w1^T + b1); out = t1 @ w2^T + b2
// ---------------------------------------------------------------------------
__global__ __launch_bounds__(256)
void head1_kernel(const float* __restrict__ h,
                  const float* __restrict__ w1, const float* __restrict__ b1,
                  float* __restrict__ t1)
{
    __shared__ float hs[DMODEL];
    int b = blockIdx.x;
    int n = threadIdx.x;
    hs[n] = h[((size_t)b * SEQ + (SEQ - 1)) * DMODEL + n];
    __syncthreads();

    const float4* wp = (const float4*)(w1 + (size_t)n * DMODEL);
    float acc = b1[n];
#pragma unroll 8
    for (int k = 0; k < DMODEL / 4; k++) {
        float4 w4 = wp[k];
        acc += hs[4*k+0]*w4.x + hs[4*k+1]*w4.y + hs[4*k+2]*w4.z + hs[4*k+3]*w4.w;
    }
    t1[b * DMODEL + n] = fmaxf(acc, 0.f);
}

__global__ __launch_bounds__(32)
void head2_kernel(const float* __restrict__ t1,
                  const float* __restrict__ w2, const float* __restrict__ b2,
                  float* __restrict__ out)
{
    int b = blockIdx.x;
    int lane = threadIdx.x;
    float acc = 0.f;
#pragma unroll
    for (int k = lane; k < DMODEL; k += 32)
        acc += t1[b * DMODEL + k] * w2[k];
#pragma unroll
    for (int off = 16; off > 0; off >>= 1)
        acc += __shfl_xor_sync(0xffffffffu, acc, off);
    if (lane == 0) out[b] = acc + b2[0];
}

// ---------------------------------------------------------------------------
// Host launcher
// ---------------------------------------------------------------------------
extern "C" void kernel_launch(void* const* d_in, const int* in_sizes, int n_in,
                              void* d_out, int out_size)
{
    const float* x            = (const float*)d_in[0];   // (8,512,32)
    const float* input_proj_w = (const float*)d_in[1];   // (256,32)
    const float* input_proj_b = (const float*)d_in[2];   // (256)
    const float* ln_w         = (const float*)d_in[3];   // (4,256)
    const float* ln_b         = (const float*)d_in[4];   // (4,256)
    const float* in_proj_w    = (const float*)d_in[5];   // (4,1024,256)
    const float* conv_w       = (const float*)d_in[6];   // (4,512,4)
    const float* conv_b       = (const float*)d_in[7];   // (4,512)
    const float* x_proj_w     = (const float*)d_in[8];   // (4,48,512)
    const float* dt_proj_w    = (const float*)d_in[9];   // (4,512,16)
    const float* dt_proj_b    = (const float*)d_in[10];  // (4,512)
    const float* A_log        = (const float*)d_in[11];  // (4,512,16)
    const float* Dvec         = (const float*)d_in[12];  // (4,512)
    const float* out_proj_w   = (const float*)d_in[13];  // (4,256,512)
    const float* head_w1      = (const float*)d_in[14];  // (256,256)
    const float* head_b1      = (const float*)d_in[15];  // (256)
    const float* head_w2      = (const float*)d_in[16];  // (1,256)
    const float* head_b2      = (const float*)d_in[17];  // (1)
    float* out = (float*)d_out;

    float *p_h, *p_xn, *p_xz, *p_u, *p_dbl, *p_dt, *p_y, *p_t1, *p_part;
    cudaGetSymbolAddress((void**)&p_h,    g_h);
    cudaGetSymbolAddress((void**)&p_xn,   g_xn);
    cudaGetSymbolAddress((void**)&p_xz,   g_xz);
    cudaGetSymbolAddress((void**)&p_u,    g_u);
    cudaGetSymbolAddress((void**)&p_dbl,  g_dbl);
    cudaGetSymbolAddress((void**)&p_dt,   g_dt);
    cudaGetSymbolAddress((void**)&p_y,    g_y);
    cudaGetSymbolAddress((void**)&p_t1,   g_t1);
    cudaGetSymbolAddress((void**)&p_part, g_part);

    // input projection: h = x @ input_proj_w^T + b   (M=4096, N=256, K=32)
    gemm_nt<<<dim3(DMODEL/BN, MROWS/BM, 1), 256>>>(
        x, INPUT_DIM, input_proj_w, INPUT_DIM, input_proj_b,
        p_h, DMODEL, 0, DMODEL, INPUT_DIM, 0);

    for (int l = 0; l < NLAYERS; l++) {
        // 1. layernorm
        ln_kernel<<<MROWS / 8, 256>>>(p_h, ln_w + l * DMODEL, ln_b + l * DMODEL, p_xn);

        // 2. in_proj: xz = xn @ W^T  (N=1024, K=256) -> 16x32 = 512 blocks
        gemm_nt<<<dim3((2*DINNER)/BN, MROWS/BM, 1), 256>>>(
            p_xn, DMODEL, in_proj_w + (size_t)l * 2 * DINNER * DMODEL, DMODEL,
            nullptr, p_xz, 2 * DINNER, 0, 2 * DINNER, DMODEL, 0);

        // 3. conv + silu -> u
        conv_silu_kernel<<<(MROWS * DINNER) / 256, 256>>>(
            p_xz, conv_w + l * DINNER * DCONV, conv_b + l * DINNER, p_u);

        // 4. x_proj: dbl = u @ W^T  (N=48, K=512), split-K=4 -> 128 blocks
        gemm_nt<<<dim3(1, MROWS/BM, 4), 256>>>(
            p_u, DINNER, x_proj_w + (size_t)l * 48 * DINNER, DINNER,
            nullptr, p_part, 48, (size_t)MROWS * 48, 48, DINNER / 4, 0);
        reduce_kernel<<<(MROWS * 48) / 1024, 256>>>(
            p_part, (size_t)MROWS * 48, 4, nullptr, p_dbl, MROWS * 48);

        // 5. dt = softplus(dbl[:, :16] @ dt_proj_w^T + b)  (N=512, K=16)
        gemm_nt<<<dim3(DINNER/BN, MROWS/BM, 1), 256>>>(
            p_dbl, 48, dt_proj_w + (size_t)l * DINNER * DTRANK, DTRANK,
            dt_proj_b + l * DINNER, p_dt, DINNER, 0, DINNER, DTRANK, 1);

        // 6. selective scan (+u*D, *silu(z))
        scan_kernel<<<(MROWS * DSTATE) / 256, 256>>>(
            p_dt, p_u, p_dbl, p_xz,
            A_log + (size_t)l * DINNER * DSTATE, Dvec + l * DINNER, p_y);

        // 7. out_proj: h += y @ W^T  (N=256, K=512), split-K=2, resid in reduce
        gemm_nt<<<dim3(DMODEL/BN, MROWS/BM, 2), 256>>>(
            p_y, DINNER, out_proj_w + (size_t)l * DMODEL * DINNER, DINNER,
            nullptr, p_part, DMODEL, (size_t)MROWS * DMODEL, DMODEL, DINNER / 2, 0);
        reduce_kernel<<<(MROWS * DMODEL) / 1024, 256>>>(
            p_part, (size_t)MROWS * DMODEL, 2, p_h, p_h, MROWS * DMODEL);
    }

    // head
    head1_kernel<<<BATCH, DMODEL>>>(p_h, head_w1, head_b1, p_t1);
    head2_kernel<<<BATCH, 32>>>(p_t1, head_w2, head_b2, out);
}

// round 3
// speedup vs baseline: 1.2062x; 1.1129x over previous
#include <cuda_runtime.h>
#include <cuda_bf16.h>
#include <cstdint>

// ---------------------------------------------------------------------------
// Model constants
// ---------------------------------------------------------------------------
#define BATCH     8
#define SEQ       512
#define INPUT_DIM 32
#define DMODEL    256
#define NLAYERS   4
#define DSTATE    16
#define DCONV     4
#define DINNER    512            // 2 * DMODEL
#define DTRANK    16
#define MROWS     (BATCH*SEQ)    // 4096
#define LN_EPS    1e-5f

// ---------------------------------------------------------------------------
// Device scratch (allocation-free rule: use __device__ globals)
// ---------------------------------------------------------------------------
__device__ float g_h   [MROWS * DMODEL];        // residual stream
__device__ float g_xn  [MROWS * DMODEL];        // layernorm output
__device__ float g_xz  [MROWS * 2 * DINNER];    // in_proj output (u | z)
__device__ float g_u   [MROWS * DINNER];        // conv+silu output
__device__ float g_dbl [MROWS * 48];            // x_proj output (dt_r | B | C)
__device__ float g_dt  [MROWS * DINNER];        // softplus(dt)
__device__ float g_y   [MROWS * DINNER];        // scan output (gated)
__device__ float g_t1  [BATCH * DMODEL];        // head hidden
__device__ float g_part[4 * MROWS * 48];        // split-K partials for x_proj

// ---------------------------------------------------------------------------
// tf32 helpers
// ---------------------------------------------------------------------------
__device__ __forceinline__ uint32_t f2tf32(float f) {
    uint32_t u;
    asm("cvt.rna.tf32.f32 %0, %1;" : "=r"(u) : "f"(f));
    return u;
}

__device__ __forceinline__ void mma_tf32(float* cc, const uint32_t* a, const uint32_t* b) {
    asm volatile("mma.sync.aligned.m16n8k8.row.col.f32.tf32.tf32.f32 "
                 "{%0,%1,%2,%3}, {%4,%5,%6,%7}, {%8,%9}, {%0,%1,%2,%3};"
                 : "+f"(cc[0]), "+f"(cc[1]), "+f"(cc[2]), "+f"(cc[3])
                 : "r"(a[0]), "r"(a[1]), "r"(a[2]), "r"(a[3]),
                   "r"(b[0]), "r"(b[1]));
}

// ---------------------------------------------------------------------------
// tf32 tensor-core NT GEMM: C[m,n] = sum_k A[m,k]*W[n,k]  (+bias,+resid,act)
// CTA tile 128x64, BK=32, 8 warps (warp tile 32x32 = 2x4 m16n8k8 frags).
// SMEM tiles row-major with stride 36 -> conflict-free fragment loads.
// Split-K via blockIdx.z: k-slice [z*Klen, (z+1)*Klen), C += z*zstride.
// Requirements: M % 128 == 0, Klen % 32 == 0.
// act: 0 none, 1 softplus
// ---------------------------------------------------------------------------
#define TBM 128
#define TBN 64
#define TBK 32
#define TLD (TBK + 4)   // 36: stride in floats; 36 mod 32 = 4 -> frag loads conflict-free

__global__ __launch_bounds__(256)
void gemm_tf32(const float* __restrict__ A, int lda,
               const float* __restrict__ W, int ldw,
               const float* __restrict__ bias,
               const float* __restrict__ resid,
               float* __restrict__ C, int ldc, size_t zstride,
               int N, int Klen, int act)
{
    __shared__ uint32_t As[TBM][TLD];   // tf32 bits, m-major
    __shared__ uint32_t Ws[TBN][TLD];   // tf32 bits, n-major

    const int tid  = threadIdx.x;
    const int wid  = tid >> 5;
    const int lane = tid & 31;
    const int wm   = wid >> 1;           // 0..3
    const int wn   = wid & 1;            // 0..1
    const int g    = lane >> 2;          // 0..7
    const int c    = lane & 3;           // 0..3

    const int row0 = blockIdx.y * TBM;
    const int col0 = blockIdx.x * TBN;
    const int kofs = blockIdx.z * Klen;
    C += (size_t)blockIdx.z * zstride;

    // global-load mapping
    const int ar = tid >> 1;             // 0..127  (A row)
    const int ak = (tid & 1) * 16;       // 0 / 16  (A k-offset, 4 float4s)
    const int wr = tid >> 2;             // 0..63   (W row)
    const int wk = (tid & 3) * 8;        // 0,8,16,24 (W k-offset, 2 float4s)
    const bool wval = (col0 + wr) < N;

    float acc[2][4][4];
#pragma unroll
    for (int mi = 0; mi < 2; mi++)
#pragma unroll
        for (int ni = 0; ni < 4; ni++)
#pragma unroll
            for (int e = 0; e < 4; e++) acc[mi][ni][e] = 0.f;

    const int ntiles = Klen / TBK;
    for (int t = 0; t < ntiles; t++) {
        // ---- global -> regs ----
        const float* Ap = A + (size_t)(row0 + ar) * lda + kofs + t * TBK + ak;
        float4 av[4];
#pragma unroll
        for (int i = 0; i < 4; i++) av[i] = ((const float4*)Ap)[i];

        float4 wv[2];
        const float* Wp = W + (size_t)(col0 + wr) * ldw + kofs + t * TBK + wk;
#pragma unroll
        for (int i = 0; i < 2; i++)
            wv[i] = wval ? ((const float4*)Wp)[i] : make_float4(0.f, 0.f, 0.f, 0.f);

        __syncthreads();   // previous tile fully consumed

        // ---- cvt + store to SMEM (STS.128) ----
#pragma unroll
        for (int i = 0; i < 4; i++) {
            uint4 uv = make_uint4(f2tf32(av[i].x), f2tf32(av[i].y),
                                  f2tf32(av[i].z), f2tf32(av[i].w));
            *(uint4*)&As[ar][ak + 4 * i] = uv;
        }
#pragma unroll
        for (int i = 0; i < 2; i++) {
            uint4 uv = make_uint4(f2tf32(wv[i].x), f2tf32(wv[i].y),
                                  f2tf32(wv[i].z), f2tf32(wv[i].w));
            *(uint4*)&Ws[wr][wk + 4 * i] = uv;
        }
        __syncthreads();

        // ---- compute: 4 k8 steps ----
#pragma unroll
        for (int ks = 0; ks < 4; ks++) {
            const int kb = ks * 8;
            uint32_t a[2][4], b[4][2];
#pragma unroll
            for (int mi = 0; mi < 2; mi++) {
                const int m0g = wm * 32 + mi * 16 + g;
                a[mi][0] = As[m0g    ][kb + c];
                a[mi][1] = As[m0g + 8][kb + c];
                a[mi][2] = As[m0g    ][kb + c + 4];
                a[mi][3] = As[m0g + 8][kb + c + 4];
            }
#pragma unroll
            for (int ni = 0; ni < 4; ni++) {
                const int n0g = wn * 32 + ni * 8 + g;
                b[ni][0] = Ws[n0g][kb + c];
                b[ni][1] = Ws[n0g][kb + c + 4];
            }
#pragma unroll
            for (int mi = 0; mi < 2; mi++)
#pragma unroll
                for (int ni = 0; ni < 4; ni++)
                    mma_tf32(acc[mi][ni], a[mi], b[ni]);
        }
    }

    // ---- epilogue ----
#pragma unroll
    for (int mi = 0; mi < 2; mi++) {
#pragma unroll
        for (int ni = 0; ni < 4; ni++) {
            const int r0 = row0 + wm * 32 + mi * 16 + g;
            const int cc = col0 + wn * 32 + ni * 8 + c * 2;
#pragma unroll
            for (int e = 0; e < 4; e++) {
                const int r  = r0 + (e >> 1) * 8;
                const int cl = cc + (e & 1);
                if (cl < N) {
                    float v = acc[mi][ni][e];
                    if (bias)  v += bias[cl];
                    if (resid) v += resid[(size_t)r * ldc + cl];
                    if (act == 1) v = (v > 20.f) ? v : log1pf(__expf(v));
                    C[(size_t)r * ldc + cl] = v;
                }
            }
        }
    }
}

// ---------------------------------------------------------------------------
// fp32 SIMT NT GEMM (kept for dt_proj, K=16). 128x64 tile, BK=16.
// ---------------------------------------------------------------------------
#define BM 128
#define BN 64
#define BK 16

__global__ __launch_bounds__(256)
void gemm_nt(const float* __restrict__ A, int lda,
             const float* __restrict__ W, int ldw,
             const float* __restrict__ bias,
             float* __restrict__ C, int ldc,
             int N, int Klen, int act)
{
    __shared__ float As[BK][BM + 8];
    __shared__ float Ws[BK][BN + 8];

    const int tid  = threadIdx.x;
    const int tx   = tid & 15;
    const int ty   = tid >> 4;
    const int m0   = ty * 8;
    const int n0   = tx * 4;
    const int row0 = blockIdx.y * BM;
    const int col0 = blockIdx.x * BN;

    const int arow = tid >> 2;
    const int akq  = (tid & 3) * 4;
    const bool wvalid = (col0 + arow) < N;

    float acc[8][4];
#pragma unroll
    for (int i = 0; i < 8; i++)
#pragma unroll
        for (int j = 0; j < 4; j++) acc[i][j] = 0.f;

    for (int k0 = 0; k0 < Klen; k0 += BK) {
        float4 a0v = *(const float4*)(A + (size_t)(row0 + arow)      * lda + k0 + akq);
        float4 a1v = *(const float4*)(A + (size_t)(row0 + arow + 64) * lda + k0 + akq);
        float4 wv  = wvalid ? *(const float4*)(W + (size_t)(col0 + arow) * ldw + k0 + akq)
                            : make_float4(0.f, 0.f, 0.f, 0.f);
#pragma unroll
        for (int cc = 0; cc < 4; cc++) {
            As[akq + cc][arow]      = (&a0v.x)[cc];
            As[akq + cc][arow + 64] = (&a1v.x)[cc];
            Ws[akq + cc][arow]      = (&wv.x)[cc];
        }
        __syncthreads();

#pragma unroll
        for (int kk = 0; kk < BK; kk++) {
            float4 a01 = *(const float4*)&As[kk][m0];
            float4 a23 = *(const float4*)&As[kk][m0 + 4];
            float4 w4  = *(const float4*)&Ws[kk][n0];
            float a[8] = {a01.x, a01.y, a01.z, a01.w, a23.x, a23.y, a23.z, a23.w};
            float w[4] = {w4.x, w4.y, w4.z, w4.w};
#pragma unroll
            for (int i = 0; i < 8; i++)
#pragma unroll
                for (int j = 0; j < 4; j++)
                    acc[i][j] = fmaf(a[i], w[j], acc[i][j]);
        }
        __syncthreads();
    }

#pragma unroll
    for (int i = 0; i < 8; i++) {
        const int r = row0 + m0 + i;
#pragma unroll
        for (int j = 0; j < 4; j++) {
            const int cl = col0 + n0 + j;
            if (cl < N) {
                float v = acc[i][j];
                if (bias) v += bias[cl];
                if (act == 1) v = (v > 20.f) ? v : log1pf(__expf(v));
                C[(size_t)r * ldc + cl] = v;
            }
        }
    }
}

// ---------------------------------------------------------------------------
// Split-K reduce: out[i] = sum_z part[z*zstride + i]
// ---------------------------------------------------------------------------
__global__ __launch_bounds__(256)
void reduce_kernel(const float* __restrict__ part, size_t zstride, int nz,
                   float* __restrict__ out, int n)
{
    int i = (blockIdx.x * blockDim.x + threadIdx.x) * 4;
    if (i >= n) return;
    float4 s = make_float4(0.f, 0.f, 0.f, 0.f);
    for (int zi = 0; zi < nz; zi++) {
        float4 p = *(const float4*)(part + (size_t)zi * zstride + i);
        s.x += p.x; s.y += p.y; s.z += p.z; s.w += p.w;
    }
    *(float4*)(out + i) = s;
}

// ---------------------------------------------------------------------------
// LayerNorm: one warp per row of 256
// ---------------------------------------------------------------------------
__global__ __launch_bounds__(256)
void ln_kernel(const float* __restrict__ h,
               const float* __restrict__ w, const float* __restrict__ b,
               float* __restrict__ out)
{
    int row  = blockIdx.x * 8 + (threadIdx.x >> 5);
    int lane = threadIdx.x & 31;
    const float* x = h + (size_t)row * DMODEL;

    float v[8];
    float s = 0.f, ss = 0.f;
#pragma unroll
    for (int i = 0; i < 8; i++) {
        v[i] = x[lane + i * 32];
        s  += v[i];
        ss += v[i] * v[i];
    }
#pragma unroll
    for (int off = 16; off > 0; off >>= 1) {
        s  += __shfl_xor_sync(0xffffffffu, s,  off);
        ss += __shfl_xor_sync(0xffffffffu, ss, off);
    }
    float mean = s * (1.f / DMODEL);
    float var  = ss * (1.f / DMODEL) - mean * mean;
    float rstd = rsqrtf(var + LN_EPS);

    float* o = out + (size_t)row * DMODEL;
#pragma unroll
    for (int i = 0; i < 8; i++) {
        int cc = lane + i * 32;
        o[cc] = (v[i] - mean) * rstd * w[cc] + b[cc];
    }
}

// ---------------------------------------------------------------------------
// Causal depthwise conv (width 4) + SiLU, reading u-half of xz
// ---------------------------------------------------------------------------
__global__ __launch_bounds__(256)
void conv_silu_kernel(const float* __restrict__ xz,
                      const float* __restrict__ cw, const float* __restrict__ cb,
                      float* __restrict__ u)
{
    int idx = blockIdx.x * blockDim.x + threadIdx.x;
    if (idx >= MROWS * DINNER) return;
    int d = idx & (DINNER - 1);
    int t = (idx >> 9) & (SEQ - 1);
    int b = idx >> 18;

    const float* base = xz + (size_t)(b * SEQ) * (2 * DINNER) + d;
    float acc = cb[d];
#pragma unroll
    for (int k = 0; k < DCONV; k++) {
        int tt = t - (DCONV - 1) + k;
        if (tt >= 0) acc += base[(size_t)tt * (2 * DINNER)] * cw[d * DCONV + k];
    }
    u[idx] = acc / (1.f + __expf(-acc));
}

// ---------------------------------------------------------------------------
// Selective scan: thread = (b, d, s). 16-lane shfl reduce over states.
// ---------------------------------------------------------------------------
__global__ __launch_bounds__(256)
void scan_kernel(const float* __restrict__ dt, const float* __restrict__ u,
                 const float* __restrict__ dbl, const float* __restrict__ xz,
                 const float* __restrict__ A_log, const float* __restrict__ Dvec,
                 float* __restrict__ y)
{
    int tid  = blockIdx.x * blockDim.x + threadIdx.x;
    int s    = tid & (DSTATE - 1);
    int pair = tid >> 4;
    int d    = pair & (DINNER - 1);
    int b    = pair >> 9;

    float A  = -__expf(A_log[d * DSTATE + s]);
    float Dp = Dvec[d];
    float h  = 0.f;

    const float* dt_p = dt  + (size_t)b * SEQ * DINNER + d;
    const float* u_p  = u   + (size_t)b * SEQ * DINNER + d;
    const float* bc_p = dbl + (size_t)b * SEQ * 48;
    const float* z_p  = xz  + (size_t)b * SEQ * (2 * DINNER) + DINNER + d;
    float*       y_p  = y   + (size_t)b * SEQ * DINNER + d;

    for (int t = 0; t < SEQ; t++) {
        float dtv = dt_p[(size_t)t * DINNER];
        float uv  = u_p [(size_t)t * DINNER];
        float Bv  = bc_p[t * 48 + DTRANK + s];
        float Cv  = bc_p[t * 48 + DTRANK + DSTATE + s];

        h = __expf(dtv * A) * h + dtv * uv * Bv;
        float yv = h * Cv;
        yv += __shfl_xor_sync(0xffffffffu, yv, 8);
        yv += __shfl_xor_sync(0xffffffffu, yv, 4);
        yv += __shfl_xor_sync(0xffffffffu, yv, 2);
        yv += __shfl_xor_sync(0xffffffffu, yv, 1);

        if (s == 0) {
            float zv  = z_p[(size_t)t * (2 * DINNER)];
            float out = (yv + uv * Dp) * (zv / (1.f + __expf(-zv)));
            y_p[(size_t)t * DINNER] = out;
        }
    }
}

// ---------------------------------------------------------------------------
// Head
// ---------------------------------------------------------------------------
__global__ __launch_bounds__(256)
void head1_kernel(const float* __restrict__ h,
                  const float* __restrict__ w1, const float* __restrict__ b1,
                  float* __restrict__ t1)
{
    __shared__ float hs[DMODEL];
    int b = blockIdx.x;
    int n = threadIdx.x;
    hs[n] = h[((size_t)b * SEQ + (SEQ - 1)) * DMODEL + n];
    __syncthreads();

    const float4* wp = (const float4*)(w1 + (size_t)n * DMODEL);
    float acc = b1[n];
#pragma unroll 8
    for (int k = 0; k < DMODEL / 4; k++) {
        float4 w4 = wp[k];
        acc += hs[4*k+0]*w4.x + hs[4*k+1]*w4.y + hs[4*k+2]*w4.z + hs[4*k+3]*w4.w;
    }
    t1[b * DMODEL + n] = fmaxf(acc, 0.f);
}

__global__ __launch_bounds__(32)
void head2_kernel(const float* __restrict__ t1,
                  const float* __restrict__ w2, const float* __restrict__ b2,
                  float* __restrict__ out)
{
    int b = blockIdx.x;
    int lane = threadIdx.x;
    float acc = 0.f;
#pragma unroll
    for (int k = lane; k < DMODEL; k += 32)
        acc += t1[b * DMODEL + k] * w2[k];
#pragma unroll
    for (int off = 16; off > 0; off >>= 1)
        acc += __shfl_xor_sync(0xffffffffu, acc, off);
    if (lane == 0) out[b] = acc + b2[0];
}

// ---------------------------------------------------------------------------
// Host launcher
// ---------------------------------------------------------------------------
extern "C" void kernel_launch(void* const* d_in, const int* in_sizes, int n_in,
                              void* d_out, int out_size)
{
    const float* x            = (const float*)d_in[0];
    const float* input_proj_w = (const float*)d_in[1];
    const float* input_proj_b = (const float*)d_in[2];
    const float* ln_w         = (const float*)d_in[3];
    const float* ln_b         = (const float*)d_in[4];
    const float* in_proj_w    = (const float*)d_in[5];
    const float* conv_w       = (const float*)d_in[6];
    const float* conv_b       = (const float*)d_in[7];
    const float* x_proj_w     = (const float*)d_in[8];
    const float* dt_proj_w    = (const float*)d_in[9];
    const float* dt_proj_b    = (const float*)d_in[10];
    const float* A_log        = (const float*)d_in[11];
    const float* Dvec         = (const float*)d_in[12];
    const float* out_proj_w   = (const float*)d_in[13];
    const float* head_w1      = (const float*)d_in[14];
    const float* head_b1      = (const float*)d_in[15];
    const float* head_w2      = (const float*)d_in[16];
    const float* head_b2      = (const float*)d_in[17];
    float* out = (float*)d_out;

    float *p_h, *p_xn, *p_xz, *p_u, *p_dbl, *p_dt, *p_y, *p_t1, *p_part;
    cudaGetSymbolAddress((void**)&p_h,    g_h);
    cudaGetSymbolAddress((void**)&p_xn,   g_xn);
    cudaGetSymbolAddress((void**)&p_xz,   g_xz);
    cudaGetSymbolAddress((void**)&p_u,    g_u);
    cudaGetSymbolAddress((void**)&p_dbl,  g_dbl);
    cudaGetSymbolAddress((void**)&p_dt,   g_dt);
    cudaGetSymbolAddress((void**)&p_y,    g_y);
    cudaGetSymbolAddress((void**)&p_t1,   g_t1);
    cudaGetSymbolAddress((void**)&p_part, g_part);

    // input projection: h = x @ input_proj_w^T + b  (K=32 -> 1 tf32 tile)
    gemm_tf32<<<dim3(DMODEL/TBN, MROWS/TBM, 1), 256>>>(
        x, INPUT_DIM, input_proj_w, INPUT_DIM, input_proj_b, nullptr,
        p_h, DMODEL, 0, DMODEL, INPUT_DIM, 0);

    for (int l = 0; l < NLAYERS; l++) {
        // 1. layernorm
        ln_kernel<<<MROWS / 8, 256>>>(p_h, ln_w + l * DMODEL, ln_b + l * DMODEL, p_xn);

        // 2. in_proj: xz = xn @ W^T  (N=1024, K=256)
        gemm_tf32<<<dim3((2*DINNER)/TBN, MROWS/TBM, 1), 256>>>(
            p_xn, DMODEL, in_proj_w + (size_t)l * 2 * DINNER * DMODEL, DMODEL,
            nullptr, nullptr, p_xz, 2 * DINNER, 0, 2 * DINNER, DMODEL, 0);

        // 3. conv + silu -> u
        conv_silu_kernel<<<(MROWS * DINNER) / 256, 256>>>(
            p_xz, conv_w + l * DINNER * DCONV, conv_b + l * DINNER, p_u);

        // 4. x_proj: dbl = u @ W^T  (N=48, K=512), split-K=4
        gemm_tf32<<<dim3(1, MROWS/TBM, 4), 256>>>(
            p_u, DINNER, x_proj_w + (size_t)l * 48 * DINNER, DINNER,
            nullptr, nullptr, p_part, 48, (size_t)MROWS * 48, 48, DINNER / 4, 0);
        reduce_kernel<<<(MROWS * 48) / 1024, 256>>>(
            p_part, (size_t)MROWS * 48, 4, p_dbl, MROWS * 48);

        // 5. dt = softplus(dbl[:, :16] @ dt_proj_w^T + b)  (K=16, fp32 SIMT)
        gemm_nt<<<dim3(DINNER/BN, MROWS/BM, 1), 256>>>(
            p_dbl, 48, dt_proj_w + (size_t)l * DINNER * DTRANK, DTRANK,
            dt_proj_b + l * DINNER, p_dt, DINNER, DINNER, DTRANK, 1);

        // 6. selective scan (+u*D, *silu(z))
        scan_kernel<<<(MROWS * DSTATE) / 256, 256>>>(
            p_dt, p_u, p_dbl, p_xz,
            A_log + (size_t)l * DINNER * DSTATE, Dvec + l * DINNER, p_y);

        // 7. out_proj: h += y @ W^T  (N=256, K=512), residual in epilogue
        gemm_tf32<<<dim3(DMODEL/TBN, MROWS/TBM, 1), 256>>>(
            p_y, DINNER, out_proj_w + (size_t)l * DMODEL * DINNER, DINNER,
            nullptr, p_h, p_h, DMODEL, 0, DMODEL, DINNER, 0);
    }

    // head
    head1_kernel<<<BATCH, DMODEL>>>(p_h, head_w1, head_b1, p_t1);
    head2_kernel<<<BATCH, 32>>>(p_t1, head_w2, head_b2, out);
}